// round 10
// baseline (speedup 1.0000x reference)
#include <cuda_runtime.h>

// Y: [16384, 2048] fp32, row-major.
// loss = sum_d | 1 - (sum_n Y[n,d]^2) / n |

#define N_ROWS   16384
#define N_COLS   2048
#define COLS4    (N_COLS / 4)        // 512 float4 per row
#define ROWS_PER_BLOCK 64
#define GRID1    (N_ROWS / ROWS_PER_BLOCK)   // 256 blocks

// Scratch (no cudaMalloc allowed): per-block partial column sums, 2 MB.
__device__ float4       g_partial[GRID1 * COLS4];
__device__ unsigned int g_done;    // phase-1 arrival counter
__device__ unsigned int g_done2;   // phase-2 completion counter (for reset)

// Single fused kernel. min-blocks=2 guarantees all 256 blocks co-resident
// (148 SMs x 2 = 296 slots), which makes the software grid barrier safe.
// The streaming body compiles to ~32 regs (proven R7), well under the 64-reg
// cap this clause implies, so MLP is unaffected.
__global__ __launch_bounds__(512, 2) void semidef_kernel(
    const float4* __restrict__ Y, float* __restrict__ out)
{
    const int tid  = threadIdx.x;                       // 0..511
    const long base = (long)blockIdx.x * ROWS_PER_BLOCK * COLS4 + tid;

    // ---- Phase 1: proven streaming body (R3/R9), ~5.9 TB/s ----
    float ax = 0.f, ay = 0.f, az = 0.f, aw = 0.f;
    #pragma unroll
    for (int r = 0; r < ROWS_PER_BLOCK; r += 4) {
        float4 v0 = Y[base + (long)(r + 0) * COLS4];
        float4 v1 = Y[base + (long)(r + 1) * COLS4];
        float4 v2 = Y[base + (long)(r + 2) * COLS4];
        float4 v3 = Y[base + (long)(r + 3) * COLS4];
        ax = fmaf(v0.x, v0.x, ax); ay = fmaf(v0.y, v0.y, ay);
        az = fmaf(v0.z, v0.z, az); aw = fmaf(v0.w, v0.w, aw);
        ax = fmaf(v1.x, v1.x, ax); ay = fmaf(v1.y, v1.y, ay);
        az = fmaf(v1.z, v1.z, az); aw = fmaf(v1.w, v1.w, aw);
        ax = fmaf(v2.x, v2.x, ax); ay = fmaf(v2.y, v2.y, ay);
        az = fmaf(v2.z, v2.z, az); aw = fmaf(v2.w, v2.w, aw);
        ax = fmaf(v3.x, v3.x, ax); ay = fmaf(v3.y, v3.y, ay);
        az = fmaf(v3.z, v3.z, az); aw = fmaf(v3.w, v3.w, aw);
    }
    float4 acc; acc.x = ax; acc.y = ay; acc.z = az; acc.w = aw;
    g_partial[(long)blockIdx.x * COLS4 + tid] = acc;

    // Zero the scalar output before any phase-2 atomicAdd can occur. This
    // store is ordered by block 0's threadfence below, and every block's
    // phase 2 starts only after observing block 0's g_done bump.
    if (blockIdx.x == 0 && tid == 0) out[0] = 0.0f;

    // ---- Software grid barrier ----
    __threadfence();                 // partials (+ out=0) visible at L2
    __syncthreads();                 // whole block's stores issued
    if (tid == 0) {
        atomicAdd(&g_done, 1u);
        volatile unsigned int* vd = &g_done;
        while (*vd < GRID1) { }
    }
    __syncthreads();

    // ---- Phase 2: block b reduces f4-columns {2b, 2b+1} over 256 rows ----
    const int fc = tid & 1;                      // 0..1
    const int rg = tid >> 1;                     // 0..255
    const int f4col = blockIdx.x * 2 + fc;       // 0..511

    float4 a = g_partial[(long)rg * COLS4 + f4col];

    __shared__ float4 s[512];                    // index = rg*2 + fc == tid
    s[tid] = a;
    __syncthreads();

    #pragma unroll
    for (int stride = 128; stride >= 1; stride >>= 1) {
        if (rg < stride) {
            float4 b2 = s[(rg + stride) * 2 + fc];
            float4 a2 = s[tid];
            a2.x += b2.x; a2.y += b2.y; a2.z += b2.z; a2.w += b2.w;
            s[tid] = a2;
        }
        __syncthreads();
    }

    if (tid == 0) {
        const float inv_n = 1.0f / (float)N_ROWS;
        float total = 0.f;
        #pragma unroll
        for (int f = 0; f < 2; f++) {
            float4 d = s[f];
            total += fabsf(1.0f - d.x * inv_n);
            total += fabsf(1.0f - d.y * inv_n);
            total += fabsf(1.0f - d.z * inv_n);
            total += fabsf(1.0f - d.w * inv_n);
        }
        atomicAdd(out, total);

        // Reset counters for the next graph replay: last finishing block only.
        // After a block bumps g_done2 it never touches g_done again, so the
        // reset cannot race with another block's spin.
        unsigned int r2 = atomicAdd(&g_done2, 1u);
        if (r2 == GRID1 - 1) {
            g_done  = 0;
            g_done2 = 0;
        }
    }
}

extern "C" void kernel_launch(void* const* d_in, const int* in_sizes, int n_in,
                              void* d_out, int out_size)
{
    const float4* Y = (const float4*)d_in[0];
    float* out = (float*)d_out;

    semidef_kernel<<<GRID1, 512>>>(Y, out);
}

// round 11
// speedup vs baseline: 1.0106x; 1.0106x over previous
#include <cuda_runtime.h>

// Y: [16384, 2048] fp32, row-major.
// loss = sum_d | 1 - (sum_n Y[n,d]^2) / n |

#define N_ROWS        16384
#define N_COLS        2048
#define COLS4         (N_COLS / 4)          // 512 float4 per row
#define ROWS_PER_SLAB 8
#define N_SLABS       (N_ROWS / ROWS_PER_SLAB)   // 2048 slabs
#define GRID1         296                    // 148 SMs x 2 blocks: ONE balanced wave
#define SLAB_BASE     (N_SLABS / GRID1)      // 6
#define SLAB_REM      (N_SLABS % GRID1)      // 272 blocks get 7 slabs

// Scratch (no cudaMalloc allowed): per-block partial column sums.
__device__ float4       g_partial[GRID1 * COLS4];
__device__ unsigned int g_done;    // phase-1 arrival counter
__device__ unsigned int g_done2;   // completion counter (for reset)

// min-blocks=2 guarantees all 296 blocks co-resident (148 SMs x 2 slots),
// making the software grid barrier deadlock-free.
__global__ __launch_bounds__(512, 2) void semidef_kernel(
    const float4* __restrict__ Y, float* __restrict__ out)
{
    const int tid = threadIdx.x;                        // 0..511
    const unsigned int b = blockIdx.x;

    // Balanced static slab range: blocks [0,272) take 7 slabs, rest take 6.
    const int nslabs = (b < SLAB_REM) ? (SLAB_BASE + 1) : SLAB_BASE;
    const long start = (long)b * SLAB_BASE + (long)min(b, (unsigned int)SLAB_REM);

    // ---- Phase 1: streaming. 8 independent LDG.128 in flight per thread,
    //      no barriers or atomics inside the loop. ----
    float ax = 0.f, ay = 0.f, az = 0.f, aw = 0.f;
    for (int i = 0; i < nslabs; i++) {
        const float4* __restrict__ p =
            Y + (start + i) * ROWS_PER_SLAB * COLS4 + tid;

        float4 v0 = p[0 * COLS4];
        float4 v1 = p[1 * COLS4];
        float4 v2 = p[2 * COLS4];
        float4 v3 = p[3 * COLS4];
        float4 v4 = p[4 * COLS4];
        float4 v5 = p[5 * COLS4];
        float4 v6 = p[6 * COLS4];
        float4 v7 = p[7 * COLS4];

        ax = fmaf(v0.x, v0.x, ax); ay = fmaf(v0.y, v0.y, ay);
        az = fmaf(v0.z, v0.z, az); aw = fmaf(v0.w, v0.w, aw);
        ax = fmaf(v1.x, v1.x, ax); ay = fmaf(v1.y, v1.y, ay);
        az = fmaf(v1.z, v1.z, az); aw = fmaf(v1.w, v1.w, aw);
        ax = fmaf(v2.x, v2.x, ax); ay = fmaf(v2.y, v2.y, ay);
        az = fmaf(v2.z, v2.z, az); aw = fmaf(v2.w, v2.w, aw);
        ax = fmaf(v3.x, v3.x, ax); ay = fmaf(v3.y, v3.y, ay);
        az = fmaf(v3.z, v3.z, az); aw = fmaf(v3.w, v3.w, aw);
        ax = fmaf(v4.x, v4.x, ax); ay = fmaf(v4.y, v4.y, ay);
        az = fmaf(v4.z, v4.z, az); aw = fmaf(v4.w, v4.w, aw);
        ax = fmaf(v5.x, v5.x, ax); ay = fmaf(v5.y, v5.y, ay);
        az = fmaf(v5.z, v5.z, az); aw = fmaf(v5.w, v5.w, aw);
        ax = fmaf(v6.x, v6.x, ax); ay = fmaf(v6.y, v6.y, ay);
        az = fmaf(v6.z, v6.z, az); aw = fmaf(v6.w, v6.w, aw);
        ax = fmaf(v7.x, v7.x, ax); ay = fmaf(v7.y, v7.y, ay);
        az = fmaf(v7.z, v7.z, az); aw = fmaf(v7.w, v7.w, aw);
    }
    float4 acc; acc.x = ax; acc.y = ay; acc.z = az; acc.w = aw;
    g_partial[(long)b * COLS4 + tid] = acc;

    // Zero the scalar output before any phase-2 atomicAdd; ordered by the
    // fence + grid barrier below.
    if (b == 0 && tid == 0) out[0] = 0.0f;

    // ---- Software grid barrier ----
    __threadfence();
    __syncthreads();
    if (tid == 0) {
        atomicAdd(&g_done, 1u);
        volatile unsigned int* vd = &g_done;
        while (*vd < GRID1) { }
    }
    __syncthreads();

    // ---- Phase 2: blocks [0,256) reduce 2 f4-columns each over 296 rows ----
    if (b < 256) {
        const int fc = tid & 1;                  // 0..1
        const int rg = tid >> 1;                 // 0..255
        const int f4col = (int)b * 2 + fc;       // 0..511

        float4 a = g_partial[(long)rg * COLS4 + f4col];
        if (rg < GRID1 - 256) {                  // fold rows 256..295
            float4 e = g_partial[(long)(rg + 256) * COLS4 + f4col];
            a.x += e.x; a.y += e.y; a.z += e.z; a.w += e.w;
        }

        __shared__ float4 s[512];                // index = rg*2 + fc == tid
        s[tid] = a;
        __syncthreads();

        #pragma unroll
        for (int stride = 128; stride >= 1; stride >>= 1) {
            if (rg < stride) {
                float4 b2 = s[(rg + stride) * 2 + fc];
                float4 a2 = s[tid];
                a2.x += b2.x; a2.y += b2.y; a2.z += b2.z; a2.w += b2.w;
                s[tid] = a2;
            }
            __syncthreads();
        }

        if (tid == 0) {
            const float inv_n = 1.0f / (float)N_ROWS;
            float total = 0.f;
            #pragma unroll
            for (int f = 0; f < 2; f++) {
                float4 d = s[f];
                total += fabsf(1.0f - d.x * inv_n);
                total += fabsf(1.0f - d.y * inv_n);
                total += fabsf(1.0f - d.z * inv_n);
                total += fabsf(1.0f - d.w * inv_n);
            }
            atomicAdd(out, total);
        }
    }

    // Reset counters for the next graph replay: last finishing block only.
    if (tid == 0) {
        unsigned int r2 = atomicAdd(&g_done2, 1u);
        if (r2 == GRID1 - 1) {
            g_done  = 0;
            g_done2 = 0;
        }
    }
}

extern "C" void kernel_launch(void* const* d_in, const int* in_sizes, int n_in,
                              void* d_out, int out_size)
{
    const float4* Y = (const float4*)d_in[0];
    float* out = (float*)d_out;

    semidef_kernel<<<GRID1, 512>>>(Y, out);
}